// round 6
// baseline (speedup 1.0000x reference)
#include <cuda_runtime.h>
#include <cuda_bf16.h>
#include <cstdint>
#include <cstddef>

#define BATCH   16384
#define WIDTH   128
#define NNODES  12
#define NEDGES  66
#define NCHUNKS 132                       // sum over v of 2v

#define BM 64
#define THREADS 256
#define A_TILE_BYTES (64 * 128)           // 64 rows x 64 bf16
#define W_TILE_BYTES (128 * 128)          // 128 n x 64 bf16
#define STAGE_BYTES (2 * A_TILE_BYTES + 2 * W_TILE_BYTES)   // 48 KB
#define NSTAGE 2
#define SMEM_TOTAL (NSTAGE * STAGE_BYTES) // 96 KB -> 2 CTAs/SM

// tile offsets within a stage
#define OFF_AHI 0
#define OFF_ALO (A_TILE_BYTES)
#define OFF_WHI (2 * A_TILE_BYTES)
#define OFF_WLO (2 * A_TILE_BYTES + W_TILE_BYTES)

// ---------------- device scratch ----------------
// slot 0 = x (converted); slots 1..10 = node outputs 1..10
__device__ __nv_bfloat16 g_Ahi[11u * BATCH * WIDTH];
__device__ __nv_bfloat16 g_Alo[11u * BATCH * WIDTH];
__device__ __nv_bfloat16 g_Whi[(size_t)NEDGES * WIDTH * WIDTH];  // [e][n][k] transposed
__device__ __nv_bfloat16 g_Wlo[(size_t)NEDGES * WIDTH * WIDTH];

// ---------------- PTX helpers ----------------
__device__ __forceinline__ uint32_t smem_u32(const void* p) {
    uint32_t a;
    asm("{ .reg .u64 t; cvta.to.shared.u64 t, %1; cvt.u32.u64 %0, t; }" : "=r"(a) : "l"(p));
    return a;
}
__device__ __forceinline__ void cp_async16(uint32_t dst, const void* src) {
    asm volatile("cp.async.cg.shared.global [%0], [%1], 16;" :: "r"(dst), "l"(src) : "memory");
}
__device__ __forceinline__ void cp_commit() {
    asm volatile("cp.async.commit_group;" ::: "memory");
}
__device__ __forceinline__ void cp_wait0() {
    asm volatile("cp.async.wait_group 0;" ::: "memory");
}
__device__ __forceinline__ void ldsm4(uint32_t& r0, uint32_t& r1, uint32_t& r2, uint32_t& r3,
                                      uint32_t addr) {
    asm volatile("ldmatrix.sync.aligned.m8n8.x4.shared.b16 {%0,%1,%2,%3}, [%4];"
                 : "=r"(r0), "=r"(r1), "=r"(r2), "=r"(r3) : "r"(addr));
}
__device__ __forceinline__ void mma_bf16(float& d0, float& d1, float& d2, float& d3,
                                         uint32_t a0, uint32_t a1, uint32_t a2, uint32_t a3,
                                         uint32_t b0, uint32_t b1) {
    asm volatile(
        "mma.sync.aligned.m16n8k16.row.col.f32.bf16.bf16.f32 "
        "{%0,%1,%2,%3}, {%4,%5,%6,%7}, {%8,%9}, {%0,%1,%2,%3};"
        : "+f"(d0), "+f"(d1), "+f"(d2), "+f"(d3)
        : "r"(a0), "r"(a1), "r"(a2), "r"(a3), "r"(b0), "r"(b1));
}

// ---------------- W conversion kernel ----------------
// W[e][k][n] fp32 -> g_W{hi,lo}[e][n][k] bf16 (transpose + split)
__global__ void conv_w_kernel(const float* __restrict__ W) {
    __shared__ float t[32][33];
    const int e  = blockIdx.x;
    const int ti = blockIdx.y;
    const int kt = (ti & 3) * 32;
    const int nt = (ti >> 2) * 32;
    const float* Wb = W + (size_t)e * WIDTH * WIDTH;
#pragma unroll
    for (int r = 0; r < 32; r += 8) {
        int k = kt + threadIdx.y + r;
        t[threadIdx.y + r][threadIdx.x] = Wb[k * WIDTH + nt + threadIdx.x];
    }
    __syncthreads();
    __nv_bfloat16* Hh = g_Whi + (size_t)e * WIDTH * WIDTH;
    __nv_bfloat16* Hl = g_Wlo + (size_t)e * WIDTH * WIDTH;
#pragma unroll
    for (int r = 0; r < 32; r += 8) {
        int n = nt + threadIdx.y + r;
        float v = t[threadIdx.x][threadIdx.y + r];
        __nv_bfloat16 h = __float2bfloat16(v);
        Hh[n * WIDTH + kt + threadIdx.x] = h;
        Hl[n * WIDTH + kt + threadIdx.x] = __float2bfloat16(v - __bfloat162float(h));
    }
}

// chunk cursor: iterates (v, e, kc) over all 132 chunks
struct Cursor {
    int v, e, kc, w;   // w = global edge index = v(v-1)/2 + e
    __device__ __forceinline__ void init() { v = 1; e = 0; kc = 0; w = 0; }
    __device__ __forceinline__ void advance() {
        if (kc == 0) { kc = 1; return; }
        kc = 0; e++; w++;
        if (e == v) { e = 0; v++; w = v * (v - 1) / 2; }
    }
};

// ---------------- fused kernel: all 11 nodes, one launch ----------------
// BM=64 rows per CTA; 8 warps in 2(M) x 4(N) grid of 32x32 tiles; 2 CTAs/SM.
__global__ void __launch_bounds__(THREADS, 2) node_fused_kernel(
    const float* __restrict__ x,
    const float* __restrict__ bias,
    float* __restrict__ out)
{
    extern __shared__ __align__(1024) char smem[];
    const uint32_t sbase = smem_u32(smem);

    const int tid  = threadIdx.x;
    const int lane = tid & 31;
    const int wid  = tid >> 5;
    const int row0 = blockIdx.x * BM;

    const int warp_moff = (wid & 1) * 32;
    const int warp_noff = (wid >> 1) * 32;

    // ---- inline x conversion for this CTA's 64 rows (row-local) ----
    {
        const float4* xs = (const float4*)(x + (size_t)row0 * WIDTH);
        const size_t ob = (size_t)row0 * WIDTH;
#pragma unroll
        for (int i = 0; i < 8; i++) {
            const int idx = i * THREADS + tid;        // 2048 float4s
            float4 v = xs[idx];
            __nv_bfloat16 h0 = __float2bfloat16(v.x);
            __nv_bfloat16 h1 = __float2bfloat16(v.y);
            __nv_bfloat16 h2 = __float2bfloat16(v.z);
            __nv_bfloat16 h3 = __float2bfloat16(v.w);
            __nv_bfloat16 l0 = __float2bfloat16(v.x - __bfloat162float(h0));
            __nv_bfloat16 l1 = __float2bfloat16(v.y - __bfloat162float(h1));
            __nv_bfloat16 l2 = __float2bfloat16(v.z - __bfloat162float(h2));
            __nv_bfloat16 l3 = __float2bfloat16(v.w - __bfloat162float(h3));
            uint2 hw = make_uint2(
                (uint32_t)__bfloat16_as_ushort(h0) | ((uint32_t)__bfloat16_as_ushort(h1) << 16),
                (uint32_t)__bfloat16_as_ushort(h2) | ((uint32_t)__bfloat16_as_ushort(h3) << 16));
            uint2 lw = make_uint2(
                (uint32_t)__bfloat16_as_ushort(l0) | ((uint32_t)__bfloat16_as_ushort(l1) << 16),
                (uint32_t)__bfloat16_as_ushort(l2) | ((uint32_t)__bfloat16_as_ushort(l3) << 16));
            *(uint2*)&g_Ahi[ob + idx * 4] = hw;
            *(uint2*)&g_Alo[ob + idx * 4] = lw;
        }
    }
    __syncthreads();

    // cp.async assignments
    const int ld_am  = tid >> 2;          // A row 0..63
    const int ld_ac0 = (tid & 3) * 2;     // 2 of 8 chunks
    const int ld_wm  = tid >> 1;          // W row 0..127
    const int ld_wc0 = (tid & 1) * 4;     // 4 of 8 chunks

    auto load_chunk = [&](const Cursor& c, int stage) {
        const uint32_t stb = sbase + stage * STAGE_BYTES;
        const size_t abase = (size_t)c.e * (BATCH * WIDTH) + (size_t)(row0 + ld_am) * WIDTH + c.kc * 64;
        const size_t wbase = (size_t)c.w * (WIDTH * WIDTH) + (size_t)ld_wm * WIDTH + c.kc * 64;
        const uint32_t adst = stb + ld_am * 128;
        const uint32_t wdst = stb + ld_wm * 128;
#pragma unroll
        for (int j = 0; j < 2; j++) {
            const int cc = ld_ac0 + j;
            const uint32_t sw = (uint32_t)((cc ^ (ld_am & 7)) << 4);
            cp_async16(adst + OFF_AHI + sw, g_Ahi + abase + cc * 8);
            cp_async16(adst + OFF_ALO + sw, g_Alo + abase + cc * 8);
        }
#pragma unroll
        for (int j = 0; j < 4; j++) {
            const int cc = ld_wc0 + j;
            const uint32_t sw = (uint32_t)((cc ^ (ld_wm & 7)) << 4);
            cp_async16(wdst + OFF_WHI + sw, g_Whi + wbase + cc * 8);
            cp_async16(wdst + OFF_WLO + sw, g_Wlo + wbase + cc * 8);
        }
    };

    float acc[2][4][4];
    float sum[2][4][4];

    Cursor cs; cs.init();
    Cursor pf; pf.init();

    load_chunk(pf, 0); cp_commit(); pf.advance();

    for (int g = 0; g < NCHUNKS; g++) {
        cp_wait0();            // stage g&1 ready (only group in flight)
        __syncthreads();       // stage (g-1)&1 fully consumed by all warps

        if (g + 1 < NCHUNKS) { load_chunk(pf, (g + 1) & 1); cp_commit(); pf.advance(); }

        if (cs.kc == 0) {
#pragma unroll
            for (int mi = 0; mi < 2; mi++)
#pragma unroll
                for (int ni = 0; ni < 4; ni++)
#pragma unroll
                    for (int q = 0; q < 4; q++) acc[mi][ni][q] = 0.f;
            if (cs.e == 0) {
#pragma unroll
                for (int mi = 0; mi < 2; mi++)
#pragma unroll
                    for (int ni = 0; ni < 4; ni++)
#pragma unroll
                        for (int q = 0; q < 4; q++) sum[mi][ni][q] = 0.f;
            }
        }

        const uint32_t stb = sbase + (g & 1) * STAGE_BYTES;
        const int q4   = lane >> 3;
        const int rsub = lane & 7;

#pragma unroll
        for (int ks = 0; ks < 4; ks++) {
            uint32_t ah[2][4], al[2][4];
            {
                const int arow = warp_moff + (q4 & 1) * 8 + rsub;
                const int ac   = ks * 2 + (q4 >> 1);
#pragma unroll
                for (int mi = 0; mi < 2; mi++) {
                    const int m = arow + mi * 16;
                    const uint32_t off = (uint32_t)(m * 128 + ((ac ^ (m & 7)) << 4));
                    ldsm4(ah[mi][0], ah[mi][1], ah[mi][2], ah[mi][3], stb + OFF_AHI + off);
                    ldsm4(al[mi][0], al[mi][1], al[mi][2], al[mi][3], stb + OFF_ALO + off);
                }
            }
            uint32_t bh[2][4], bl[2][4];
            {
                const int bn0 = warp_noff + (q4 >> 1) * 8 + rsub;
                const int bc  = ks * 2 + (q4 & 1);
#pragma unroll
                for (int np = 0; np < 2; np++) {
                    const int n = bn0 + np * 16;
                    const uint32_t off = (uint32_t)(n * 128 + ((bc ^ (n & 7)) << 4));
                    ldsm4(bh[np][0], bh[np][1], bh[np][2], bh[np][3], stb + OFF_WHI + off);
                    ldsm4(bl[np][0], bl[np][1], bl[np][2], bl[np][3], stb + OFF_WLO + off);
                }
            }
#pragma unroll
            for (int mi = 0; mi < 2; mi++)
#pragma unroll
                for (int ni = 0; ni < 4; ni++) {
                    const int np = ni >> 1, h = (ni & 1) * 2;
                    float* d = acc[mi][ni];
                    mma_bf16(d[0], d[1], d[2], d[3],
                             ah[mi][0], ah[mi][1], ah[mi][2], ah[mi][3],
                             bh[np][h], bh[np][h + 1]);
                    mma_bf16(d[0], d[1], d[2], d[3],
                             ah[mi][0], ah[mi][1], ah[mi][2], ah[mi][3],
                             bl[np][h], bl[np][h + 1]);
                    mma_bf16(d[0], d[1], d[2], d[3],
                             al[mi][0], al[mi][1], al[mi][2], al[mi][3],
                             bh[np][h], bh[np][h + 1]);
                }
        }

        if (cs.kc == 1) {
            const float* bp = bias + (size_t)cs.w * WIDTH + warp_noff + 2 * (lane & 3);
#pragma unroll
            for (int ni = 0; ni < 4; ni++) {
                const float2 bb = *(const float2*)(bp + ni * 8);
#pragma unroll
                for (int mi = 0; mi < 2; mi++) {
                    sum[mi][ni][0] += fmaxf(acc[mi][ni][0] + bb.x, 0.f);
                    sum[mi][ni][1] += fmaxf(acc[mi][ni][1] + bb.y, 0.f);
                    sum[mi][ni][2] += fmaxf(acc[mi][ni][2] + bb.x, 0.f);
                    sum[mi][ni][3] += fmaxf(acc[mi][ni][3] + bb.y, 0.f);
                }
            }

            if (cs.e == cs.v - 1) {
                const int colb = warp_noff + 2 * (lane & 3);
                if (cs.v == NNODES - 1) {
#pragma unroll
                    for (int mi = 0; mi < 2; mi++) {
                        const int r0 = row0 + warp_moff + mi * 16 + (lane >> 2);
#pragma unroll
                        for (int ni = 0; ni < 4; ni++) {
                            const int col = colb + ni * 8;
                            *(float2*)(out + (size_t)r0 * WIDTH + col) =
                                make_float2(sum[mi][ni][0], sum[mi][ni][1]);
                            *(float2*)(out + (size_t)(r0 + 8) * WIDTH + col) =
                                make_float2(sum[mi][ni][2], sum[mi][ni][3]);
                        }
                    }
                } else {
                    const size_t nb = (size_t)cs.v * (BATCH * WIDTH);
#pragma unroll
                    for (int mi = 0; mi < 2; mi++) {
                        const int r0 = row0 + warp_moff + mi * 16 + (lane >> 2);
#pragma unroll
                        for (int ni = 0; ni < 4; ni++) {
                            const int col = colb + ni * 8;
#pragma unroll
                            for (int h = 0; h < 2; h++) {
                                const float s0 = sum[mi][ni][h * 2];
                                const float s1 = sum[mi][ni][h * 2 + 1];
                                const __nv_bfloat16 h0 = __float2bfloat16(s0);
                                const __nv_bfloat16 h1 = __float2bfloat16(s1);
                                const __nv_bfloat16 l0 = __float2bfloat16(s0 - __bfloat162float(h0));
                                const __nv_bfloat16 l1 = __float2bfloat16(s1 - __bfloat162float(h1));
                                const size_t o = nb + (size_t)(r0 + h * 8) * WIDTH + col;
                                *(uint32_t*)&g_Ahi[o] = (uint32_t)__bfloat16_as_ushort(h0) |
                                                        ((uint32_t)__bfloat16_as_ushort(h1) << 16);
                                *(uint32_t*)&g_Alo[o] = (uint32_t)__bfloat16_as_ushort(l0) |
                                                        ((uint32_t)__bfloat16_as_ushort(l1) << 16);
                            }
                        }
                    }
                }
            }
        }

        cs.advance();
    }
}

// ---------------- launch ----------------
extern "C" void kernel_launch(void* const* d_in, const int* in_sizes, int n_in,
                              void* d_out, int out_size) {
    const float* x = (const float*)d_in[0];
    const float* W = (const float*)d_in[1];
    const float* b = (const float*)d_in[2];
    float* out = (float*)d_out;

    cudaFuncSetAttribute(node_fused_kernel,
                         cudaFuncAttributeMaxDynamicSharedMemorySize, SMEM_TOTAL);

    conv_w_kernel<<<dim3(NEDGES, 16), dim3(32, 8)>>>(W);
    node_fused_kernel<<<BATCH / BM, THREADS, SMEM_TOTAL>>>(x, b, out);
}

// round 7
// speedup vs baseline: 1.1986x; 1.1986x over previous
#include <cuda_runtime.h>
#include <cuda_bf16.h>
#include <cstdint>
#include <cstddef>

#define BATCH   16384
#define WIDTH   128
#define NNODES  12
#define NEDGES  66
#define NCHUNKS 132                       // sum over v of 2v

#define BM 128
#define THREADS 544                       // 16 consumer warps + 1 producer warp
#define TILE_BYTES (128 * 128)            // 128 rows x 64 bf16 = 16 KB
#define STAGE_BYTES (4 * TILE_BYTES)      // Ahi, Alo, Whi, Wlo = 64 KB
#define NSTAGE 3
#define STAGE0_OFF 1024
#define SMEM_TOTAL (STAGE0_OFF + NSTAGE * STAGE_BYTES)   // 197632 B

// mbarrier offsets in smem
#define MB_FULL(s)  ((s) * 8)             // 0, 8, 16
#define MB_EMPTY(s) (24 + (s) * 8)        // 24, 32, 40

#define OFF_AHI 0
#define OFF_ALO TILE_BYTES
#define OFF_WHI (2 * TILE_BYTES)
#define OFF_WLO (3 * TILE_BYTES)

// ---------------- device scratch ----------------
// slot 0 = x (converted); slots 1..10 = node outputs 1..10
__device__ __nv_bfloat16 g_Ahi[11u * BATCH * WIDTH];
__device__ __nv_bfloat16 g_Alo[11u * BATCH * WIDTH];
__device__ __nv_bfloat16 g_Whi[(size_t)NEDGES * WIDTH * WIDTH];  // [e][n][k] transposed
__device__ __nv_bfloat16 g_Wlo[(size_t)NEDGES * WIDTH * WIDTH];

// ---------------- PTX helpers ----------------
__device__ __forceinline__ uint32_t smem_u32(const void* p) {
    uint32_t a;
    asm("{ .reg .u64 t; cvta.to.shared.u64 t, %1; cvt.u32.u64 %0, t; }" : "=r"(a) : "l"(p));
    return a;
}
__device__ __forceinline__ void mbar_init(uint32_t a, uint32_t cnt) {
    asm volatile("mbarrier.init.shared.b64 [%0], %1;" :: "r"(a), "r"(cnt) : "memory");
}
__device__ __forceinline__ void mbar_arrive(uint32_t a) {
    asm volatile("mbarrier.arrive.shared.b64 _, [%0];" :: "r"(a) : "memory");
}
__device__ __forceinline__ void mbar_wait(uint32_t a, uint32_t parity) {
    asm volatile(
        "{\n\t.reg .pred P;\n\t"
        "WL%=:\n\t"
        "mbarrier.try_wait.parity.acquire.cta.shared::cta.b64 P, [%0], %1, 0x989680;\n\t"
        "@!P bra WL%=;\n\t}"
        :: "r"(a), "r"(parity) : "memory");
}
__device__ __forceinline__ void cp_async16(uint32_t dst, const void* src) {
    asm volatile("cp.async.cg.shared.global [%0], [%1], 16;" :: "r"(dst), "l"(src) : "memory");
}
__device__ __forceinline__ void cp_async_arrive_noinc(uint32_t mbar) {
    asm volatile("cp.async.mbarrier.arrive.noinc.shared.b64 [%0];" :: "r"(mbar) : "memory");
}
__device__ __forceinline__ void ldsm4(uint32_t& r0, uint32_t& r1, uint32_t& r2, uint32_t& r3,
                                      uint32_t addr) {
    asm volatile("ldmatrix.sync.aligned.m8n8.x4.shared.b16 {%0,%1,%2,%3}, [%4];"
                 : "=r"(r0), "=r"(r1), "=r"(r2), "=r"(r3) : "r"(addr));
}
__device__ __forceinline__ void mma_bf16(float& d0, float& d1, float& d2, float& d3,
                                         uint32_t a0, uint32_t a1, uint32_t a2, uint32_t a3,
                                         uint32_t b0, uint32_t b1) {
    asm volatile(
        "mma.sync.aligned.m16n8k16.row.col.f32.bf16.bf16.f32 "
        "{%0,%1,%2,%3}, {%4,%5,%6,%7}, {%8,%9}, {%0,%1,%2,%3};"
        : "+f"(d0), "+f"(d1), "+f"(d2), "+f"(d3)
        : "r"(a0), "r"(a1), "r"(a2), "r"(a3), "r"(b0), "r"(b1));
}

// ---------------- W conversion kernel ----------------
__global__ void conv_w_kernel(const float* __restrict__ W) {
    __shared__ float t[32][33];
    const int e  = blockIdx.x;
    const int ti = blockIdx.y;
    const int kt = (ti & 3) * 32;
    const int nt = (ti >> 2) * 32;
    const float* Wb = W + (size_t)e * WIDTH * WIDTH;
#pragma unroll
    for (int r = 0; r < 32; r += 8) {
        int k = kt + threadIdx.y + r;
        t[threadIdx.y + r][threadIdx.x] = Wb[k * WIDTH + nt + threadIdx.x];
    }
    __syncthreads();
    __nv_bfloat16* Hh = g_Whi + (size_t)e * WIDTH * WIDTH;
    __nv_bfloat16* Hl = g_Wlo + (size_t)e * WIDTH * WIDTH;
#pragma unroll
    for (int r = 0; r < 32; r += 8) {
        int n = nt + threadIdx.y + r;
        float v = t[threadIdx.x][threadIdx.y + r];
        __nv_bfloat16 h = __float2bfloat16(v);
        Hh[n * WIDTH + kt + threadIdx.x] = h;
        Hl[n * WIDTH + kt + threadIdx.x] = __float2bfloat16(v - __bfloat162float(h));
    }
}

// chunk cursor: iterates (v, e, kc) over all 132 chunks
struct Cursor {
    int v, e, kc, w;   // w = global edge index = v(v-1)/2 + e
    __device__ __forceinline__ void init() { v = 1; e = 0; kc = 0; w = 0; }
    __device__ __forceinline__ void advance() {
        if (kc == 0) { kc = 1; return; }
        kc = 0; e++; w++;
        if (e == v) { e = 0; v++; w = v * (v - 1) / 2; }
    }
};

// ---------------- fused kernel: all 11 nodes, one launch ----------------
// 16 consumer warps (4x4 grid of 32x32 tiles) + 1 producer warp.
__global__ void __launch_bounds__(THREADS, 1) node_fused_kernel(
    const float* __restrict__ x,
    const float* __restrict__ bias,
    float* __restrict__ out)
{
    extern __shared__ __align__(1024) char smem[];
    const uint32_t sbase = smem_u32(smem);

    const int tid  = threadIdx.x;
    const int lane = tid & 31;
    const int wid  = tid >> 5;
    const int row0 = blockIdx.x * BM;

    if (tid == 0) {
#pragma unroll
        for (int s = 0; s < NSTAGE; s++) {
            mbar_init(sbase + MB_FULL(s), 32);    // producer warp threads
            mbar_init(sbase + MB_EMPTY(s), 16);   // one per consumer warp
        }
    }

    // ---- inline x conversion for this CTA's 128 rows (row-local) ----
    {
        const float4* xs = (const float4*)(x + (size_t)row0 * WIDTH);
        const size_t ob = (size_t)row0 * WIDTH;
        for (int idx = tid; idx < 4096; idx += THREADS) {
            float4 v = xs[idx];
            __nv_bfloat16 h0 = __float2bfloat16(v.x);
            __nv_bfloat16 h1 = __float2bfloat16(v.y);
            __nv_bfloat16 h2 = __float2bfloat16(v.z);
            __nv_bfloat16 h3 = __float2bfloat16(v.w);
            __nv_bfloat16 l0 = __float2bfloat16(v.x - __bfloat162float(h0));
            __nv_bfloat16 l1 = __float2bfloat16(v.y - __bfloat162float(h1));
            __nv_bfloat16 l2 = __float2bfloat16(v.z - __bfloat162float(h2));
            __nv_bfloat16 l3 = __float2bfloat16(v.w - __bfloat162float(h3));
            uint2 hw = make_uint2(
                (uint32_t)__bfloat16_as_ushort(h0) | ((uint32_t)__bfloat16_as_ushort(h1) << 16),
                (uint32_t)__bfloat16_as_ushort(h2) | ((uint32_t)__bfloat16_as_ushort(h3) << 16));
            uint2 lw = make_uint2(
                (uint32_t)__bfloat16_as_ushort(l0) | ((uint32_t)__bfloat16_as_ushort(l1) << 16),
                (uint32_t)__bfloat16_as_ushort(l2) | ((uint32_t)__bfloat16_as_ushort(l3) << 16));
            *(uint2*)&g_Ahi[ob + (size_t)idx * 4] = hw;
            *(uint2*)&g_Alo[ob + (size_t)idx * 4] = lw;
        }
    }
    __syncthreads();   // mbarrier init + converted x visible to all

    if (wid == 16) {
        // ================= PRODUCER WARP =================
        Cursor pf; pf.init();
        int empty_par[NSTAGE] = {0, 0, 0};
        for (int g = 0; g < NCHUNKS; g++) {
            const int s = g % NSTAGE;
            if (g >= NSTAGE) {
                mbar_wait(sbase + MB_EMPTY(s), empty_par[s]);
                empty_par[s] ^= 1;
            }
            const uint32_t stb = sbase + STAGE0_OFF + s * STAGE_BYTES;
            const size_t abase = (size_t)pf.e * (BATCH * WIDTH) + (size_t)row0 * WIDTH + pf.kc * 64;
            const size_t wbase = (size_t)pf.w * (WIDTH * WIDTH) + pf.kc * 64;
            // each of 32 lanes: 32 lines per tile (line idx = j*32 + lane)
#pragma unroll
            for (int j = 0; j < 32; j++) {
                const int idx = j * 32 + lane;       // 0..1023
                const int m  = idx >> 3;             // row 0..127
                const int cc = idx & 7;              // 16B chunk in row
                const uint32_t sw  = (uint32_t)(m * 128 + ((cc ^ (m & 7)) << 4));
                const size_t  asrc = abase + (size_t)m * WIDTH + cc * 8;
                const size_t  wsrc = wbase + (size_t)m * WIDTH + cc * 8;
                cp_async16(stb + OFF_AHI + sw, g_Ahi + asrc);
                cp_async16(stb + OFF_ALO + sw, g_Alo + asrc);
                cp_async16(stb + OFF_WHI + sw, g_Whi + wsrc);
                cp_async16(stb + OFF_WLO + sw, g_Wlo + wsrc);
            }
            cp_async_arrive_noinc(sbase + MB_FULL(s));
            pf.advance();
        }
        return;
    }

    // ================= CONSUMER WARPS (0..15) =================
    const int warp_moff = (wid & 3) * 32;
    const int warp_noff = (wid >> 2) * 32;

    float acc[2][4][4];
    float sum[2][4][4];
    int full_par[NSTAGE] = {0, 0, 0};

    Cursor cs; cs.init();

    for (int g = 0; g < NCHUNKS; g++) {
        const int s = g % NSTAGE;
        mbar_wait(sbase + MB_FULL(s), full_par[s]);
        full_par[s] ^= 1;

        if (cs.kc == 0) {
#pragma unroll
            for (int mi = 0; mi < 2; mi++)
#pragma unroll
                for (int ni = 0; ni < 4; ni++)
#pragma unroll
                    for (int q = 0; q < 4; q++) acc[mi][ni][q] = 0.f;
            if (cs.e == 0) {
#pragma unroll
                for (int mi = 0; mi < 2; mi++)
#pragma unroll
                    for (int ni = 0; ni < 4; ni++)
#pragma unroll
                        for (int q = 0; q < 4; q++) sum[mi][ni][q] = 0.f;
            }
        }

        const uint32_t stb = sbase + STAGE0_OFF + s * STAGE_BYTES;
        const int q4   = lane >> 3;
        const int rsub = lane & 7;

#pragma unroll
        for (int ks = 0; ks < 4; ks++) {
            uint32_t ah[2][4], al[2][4];
            {
                const int arow = warp_moff + (q4 & 1) * 8 + rsub;
                const int ac   = ks * 2 + (q4 >> 1);
#pragma unroll
                for (int mi = 0; mi < 2; mi++) {
                    const int m = arow + mi * 16;
                    const uint32_t off = (uint32_t)(m * 128 + ((ac ^ (m & 7)) << 4));
                    ldsm4(ah[mi][0], ah[mi][1], ah[mi][2], ah[mi][3], stb + OFF_AHI + off);
                    ldsm4(al[mi][0], al[mi][1], al[mi][2], al[mi][3], stb + OFF_ALO + off);
                }
            }
            uint32_t bh[2][4], bl[2][4];
            {
                const int bn0 = warp_noff + (q4 >> 1) * 8 + rsub;
                const int bc  = ks * 2 + (q4 & 1);
#pragma unroll
                for (int np = 0; np < 2; np++) {
                    const int n = bn0 + np * 16;
                    const uint32_t off = (uint32_t)(n * 128 + ((bc ^ (n & 7)) << 4));
                    ldsm4(bh[np][0], bh[np][1], bh[np][2], bh[np][3], stb + OFF_WHI + off);
                    ldsm4(bl[np][0], bl[np][1], bl[np][2], bl[np][3], stb + OFF_WLO + off);
                }
            }
#pragma unroll
            for (int mi = 0; mi < 2; mi++)
#pragma unroll
                for (int ni = 0; ni < 4; ni++) {
                    const int np = ni >> 1, h = (ni & 1) * 2;
                    float* d = acc[mi][ni];
                    mma_bf16(d[0], d[1], d[2], d[3],
                             ah[mi][0], ah[mi][1], ah[mi][2], ah[mi][3],
                             bh[np][h], bh[np][h + 1]);
                    mma_bf16(d[0], d[1], d[2], d[3],
                             ah[mi][0], ah[mi][1], ah[mi][2], ah[mi][3],
                             bl[np][h], bl[np][h + 1]);
                    mma_bf16(d[0], d[1], d[2], d[3],
                             al[mi][0], al[mi][1], al[mi][2], al[mi][3],
                             bh[np][h], bh[np][h + 1]);
                }
        }

        if (cs.kc == 1) {
            // per-edge epilogue: bias + relu + accumulate
            const float* bp = bias + (size_t)cs.w * WIDTH + warp_noff + 2 * (lane & 3);
#pragma unroll
            for (int ni = 0; ni < 4; ni++) {
                const float2 bb = *(const float2*)(bp + ni * 8);
#pragma unroll
                for (int mi = 0; mi < 2; mi++) {
                    sum[mi][ni][0] += fmaxf(acc[mi][ni][0] + bb.x, 0.f);
                    sum[mi][ni][1] += fmaxf(acc[mi][ni][1] + bb.y, 0.f);
                    sum[mi][ni][2] += fmaxf(acc[mi][ni][2] + bb.x, 0.f);
                    sum[mi][ni][3] += fmaxf(acc[mi][ni][3] + bb.y, 0.f);
                }
            }

            if (cs.e == cs.v - 1) {
                // ---- node writeout (before empty-arrive: release ordering) ----
                const int colb = warp_noff + 2 * (lane & 3);
                if (cs.v == NNODES - 1) {
#pragma unroll
                    for (int mi = 0; mi < 2; mi++) {
                        const int r0 = row0 + warp_moff + mi * 16 + (lane >> 2);
#pragma unroll
                        for (int ni = 0; ni < 4; ni++) {
                            const int col = colb + ni * 8;
                            *(float2*)(out + (size_t)r0 * WIDTH + col) =
                                make_float2(sum[mi][ni][0], sum[mi][ni][1]);
                            *(float2*)(out + (size_t)(r0 + 8) * WIDTH + col) =
                                make_float2(sum[mi][ni][2], sum[mi][ni][3]);
                        }
                    }
                } else {
                    const size_t nb = (size_t)cs.v * (BATCH * WIDTH);
#pragma unroll
                    for (int mi = 0; mi < 2; mi++) {
                        const int r0 = row0 + warp_moff + mi * 16 + (lane >> 2);
#pragma unroll
                        for (int ni = 0; ni < 4; ni++) {
                            const int col = colb + ni * 8;
#pragma unroll
                            for (int h = 0; h < 2; h++) {
                                const float s0 = sum[mi][ni][h * 2];
                                const float s1 = sum[mi][ni][h * 2 + 1];
                                const __nv_bfloat16 h0 = __float2bfloat16(s0);
                                const __nv_bfloat16 h1 = __float2bfloat16(s1);
                                const __nv_bfloat16 l0 = __float2bfloat16(s0 - __bfloat162float(h0));
                                const __nv_bfloat16 l1 = __float2bfloat16(s1 - __bfloat162float(h1));
                                const size_t o = nb + (size_t)(r0 + h * 8) * WIDTH + col;
                                *(uint32_t*)&g_Ahi[o] = (uint32_t)__bfloat16_as_ushort(h0) |
                                                        ((uint32_t)__bfloat16_as_ushort(h1) << 16);
                                *(uint32_t*)&g_Alo[o] = (uint32_t)__bfloat16_as_ushort(l0) |
                                                        ((uint32_t)__bfloat16_as_ushort(l1) << 16);
                            }
                        }
                    }
                    __threadfence();   // writeout globally visible before release
                }
            }
        }

        if (lane == 0) mbar_arrive(sbase + MB_EMPTY(s));
        cs.advance();
    }
}

// ---------------- launch ----------------
extern "C" void kernel_launch(void* const* d_in, const int* in_sizes, int n_in,
                              void* d_out, int out_size) {
    const float* x = (const float*)d_in[0];
    const float* W = (const float*)d_in[1];
    const float* b = (const float*)d_in[2];
    float* out = (float*)d_out;

    cudaFuncSetAttribute(node_fused_kernel,
                         cudaFuncAttributeMaxDynamicSharedMemorySize, SMEM_TOTAL);

    conv_w_kernel<<<dim3(NEDGES, 16), dim3(32, 8)>>>(W);
    node_fused_kernel<<<BATCH / BM, THREADS, SMEM_TOTAL>>>(x, b, out);
}